// round 3
// baseline (speedup 1.0000x reference)
#include <cuda_runtime.h>
#include <math.h>

#define NB    4
#define NRES  56
#define NTOK  3136            // 56*56
#define DIMF  384
#define TDF   192
#define MTOT  12544           // NB*NTOK

typedef unsigned long long ull;

// packed f32x2 helpers (sm_100+ PTX; FFMA2 is PTX-only per SASS_QUICKREF)
__device__ __forceinline__ ull ffma2(ull a, ull b, ull c) {
    ull d; asm("fma.rn.f32x2 %0, %1, %2, %3;" : "=l"(d) : "l"(a), "l"(b), "l"(c)); return d;
}
__device__ __forceinline__ ull fmul2(ull a, ull b) {
    ull d; asm("mul.rn.f32x2 %0, %1, %2;" : "=l"(d) : "l"(a), "l"(b)); return d;
}
__device__ __forceinline__ ull pack2(float x, float y) {
    ull r; asm("mov.b64 %0, {%1, %2};" : "=l"(r) : "f"(x), "f"(y)); return r;
}
__device__ __forceinline__ float2 unpack2(ull v) {
    float2 r; asm("mov.b64 {%0, %1}, %2;" : "=f"(r.x), "=f"(r.y) : "l"(v)); return r;
}

// scratch (allocation-free rule: __device__ globals)
__device__ __align__(16) float g_tmp[(size_t)MTOT * DIMF];    // (m,384): 0..191 up, 192..383 dn
__device__ __align__(16) float g_qkv[(size_t)MTOT * 1152];    // (m,1152): 0..575 up qkv, 576..1151 dn qkv

// ---------------------------------------------------------------------------
// GEMM1: g_tmp[m,o] = sum_k xa[b,k,n] * W[o,k];  W = proj1 (o<192) / proj2
// Tile 256x64x16, 256 threads, micro 16x4, f32x2 (pairs along m).
// ---------------------------------------------------------------------------
__global__ __launch_bounds__(256) void gemm1_kernel(
    const float* __restrict__ xa, const float* __restrict__ p1,
    const float* __restrict__ p2)
{
    __shared__ __align__(16) float As[16][260];
    __shared__ __align__(16) float Bs[16][68];
    int tid = threadIdx.x;
    int m0 = blockIdx.x * 256;
    int o0 = blockIdx.y * 64;
    const float* wb = (o0 < TDF) ? p1 : p2;
    int orow0 = (o0 < TDF) ? o0 : (o0 - TDF);

    // per-thread A source (handles batch boundary inside tile)
    int mm = m0 + tid;
    int bb = mm / NTOK;
    int nn = mm - bb * NTOK;
    const float* asrc = xa + (size_t)bb * DIMF * NTOK + nn;

    int b_ol = tid >> 2;          // 0..63
    int b_kq = tid & 3;           // 0..3

    ull acc2[8][4];
    #pragma unroll
    for (int i = 0; i < 8; i++)
        #pragma unroll
        for (int j = 0; j < 4; j++) acc2[i][j] = 0ull;

    int mr = (tid >> 4) * 16;
    int oc = (tid & 15) * 4;

    for (int k0 = 0; k0 < DIMF; k0 += 16) {
        #pragma unroll
        for (int k = 0; k < 16; k++)
            As[k][tid] = asrc[(size_t)(k0 + k) * NTOK];
        {
            float4 w4 = *(const float4*)(wb + (size_t)(orow0 + b_ol) * DIMF + k0 + b_kq * 4);
            Bs[b_kq*4+0][b_ol] = w4.x;
            Bs[b_kq*4+1][b_ol] = w4.y;
            Bs[b_kq*4+2][b_ol] = w4.z;
            Bs[b_kq*4+3][b_ol] = w4.w;
        }
        __syncthreads();
        #pragma unroll
        for (int k = 0; k < 16; k++) {
            const ulonglong2* ap = (const ulonglong2*)&As[k][mr];
            ull a2[8];
            #pragma unroll
            for (int q = 0; q < 4; q++) {
                ulonglong2 t = ap[q];
                a2[2*q] = t.x; a2[2*q+1] = t.y;
            }
            float4 bv = *(const float4*)&Bs[k][oc];
            ull b2[4];
            b2[0] = pack2(bv.x, bv.x); b2[1] = pack2(bv.y, bv.y);
            b2[2] = pack2(bv.z, bv.z); b2[3] = pack2(bv.w, bv.w);
            #pragma unroll
            for (int i = 0; i < 8; i++)
                #pragma unroll
                for (int j = 0; j < 4; j++)
                    acc2[i][j] = ffma2(a2[i], b2[j], acc2[i][j]);
        }
        __syncthreads();
    }
    #pragma unroll
    for (int i = 0; i < 8; i++) {
        float2 u0 = unpack2(acc2[i][0]);
        float2 u1 = unpack2(acc2[i][1]);
        float2 u2 = unpack2(acc2[i][2]);
        float2 u3 = unpack2(acc2[i][3]);
        *(float4*)(g_tmp + (size_t)(m0 + mr + 2*i)     * DIMF + o0 + oc) = make_float4(u0.x, u1.x, u2.x, u3.x);
        *(float4*)(g_tmp + (size_t)(m0 + mr + 2*i + 1) * DIMF + o0 + oc) = make_float4(u0.y, u1.y, u2.y, u3.y);
    }
}

// ---------------------------------------------------------------------------
// GEMM2: g_qkv[m,o] = sum_k g_tmp[m,koff+k] * W[o',k]  (K=192)
//   o<576: W=qkv_up, koff=0;  o>=576: W=qkv_dn, koff=192
// ---------------------------------------------------------------------------
__global__ __launch_bounds__(256) void gemm2_kernel(
    const float* __restrict__ wu, const float* __restrict__ wd)
{
    __shared__ __align__(16) float As[16][260];
    __shared__ __align__(16) float Bs[16][68];
    int tid = threadIdx.x;
    int m0 = blockIdx.x * 256;
    int o0 = blockIdx.y * 64;
    const float* wb; int orow0, koff;
    if (o0 < 576) { wb = wu; orow0 = o0;       koff = 0;   }
    else          { wb = wd; orow0 = o0 - 576; koff = TDF; }

    int b_ol = tid >> 2;
    int b_kq = tid & 3;

    ull acc2[8][4];
    #pragma unroll
    for (int i = 0; i < 8; i++)
        #pragma unroll
        for (int j = 0; j < 4; j++) acc2[i][j] = 0ull;

    int mr = (tid >> 4) * 16;
    int oc = (tid & 15) * 4;
    const float* asrc = g_tmp + (size_t)(m0 + tid) * DIMF + koff;

    for (int k0 = 0; k0 < TDF; k0 += 16) {
        #pragma unroll
        for (int q = 0; q < 4; q++) {
            float4 a4 = *(const float4*)(asrc + k0 + q * 4);
            As[q*4+0][tid] = a4.x;
            As[q*4+1][tid] = a4.y;
            As[q*4+2][tid] = a4.z;
            As[q*4+3][tid] = a4.w;
        }
        {
            float4 w4 = *(const float4*)(wb + (size_t)(orow0 + b_ol) * TDF + k0 + b_kq * 4);
            Bs[b_kq*4+0][b_ol] = w4.x;
            Bs[b_kq*4+1][b_ol] = w4.y;
            Bs[b_kq*4+2][b_ol] = w4.z;
            Bs[b_kq*4+3][b_ol] = w4.w;
        }
        __syncthreads();
        #pragma unroll
        for (int k = 0; k < 16; k++) {
            const ulonglong2* ap = (const ulonglong2*)&As[k][mr];
            ull a2[8];
            #pragma unroll
            for (int q = 0; q < 4; q++) {
                ulonglong2 t = ap[q];
                a2[2*q] = t.x; a2[2*q+1] = t.y;
            }
            float4 bv = *(const float4*)&Bs[k][oc];
            ull b2[4];
            b2[0] = pack2(bv.x, bv.x); b2[1] = pack2(bv.y, bv.y);
            b2[2] = pack2(bv.z, bv.z); b2[3] = pack2(bv.w, bv.w);
            #pragma unroll
            for (int i = 0; i < 8; i++)
                #pragma unroll
                for (int j = 0; j < 4; j++)
                    acc2[i][j] = ffma2(a2[i], b2[j], acc2[i][j]);
        }
        __syncthreads();
    }
    #pragma unroll
    for (int i = 0; i < 8; i++) {
        float2 u0 = unpack2(acc2[i][0]);
        float2 u1 = unpack2(acc2[i][1]);
        float2 u2 = unpack2(acc2[i][2]);
        float2 u3 = unpack2(acc2[i][3]);
        *(float4*)(g_qkv + (size_t)(m0 + mr + 2*i)     * 1152 + o0 + oc) = make_float4(u0.x, u1.x, u2.x, u3.x);
        *(float4*)(g_qkv + (size_t)(m0 + mr + 2*i + 1) * 1152 + o0 + oc) = make_float4(u0.y, u1.y, u2.y, u3.y);
    }
}

// ---------------------------------------------------------------------------
// CSWin attention + fused LePE. One block per (window g, head hd, branch br).
// n=392 tokens, d=48. K/V resident in smem; one query per thread; online
// softmax; depthwise 3x3 LePE computed from the smem V tile; write-once out.
// ---------------------------------------------------------------------------
__global__ __launch_bounds__(416, 1) void cswin_kernel(
    const float* __restrict__ lw0, const float* __restrict__ lb0,
    const float* __restrict__ lw1, const float* __restrict__ lb1,
    float* __restrict__ out)
{
    extern __shared__ float smem[];
    float* sK = smem;                    // [392][48]
    float* sV = smem + 392 * 48;         // [392][48]
    float* sw = smem + 2 * 392 * 48;     // [9][48]
    float* sb = sw + 9 * 48;             // [48]

    int tid = threadIdx.x;
    int g  = blockIdx.x;   // 0..31
    int hd = blockIdx.y;   // 0..1
    int br = blockIdx.z;   // 0..1
    int wi = g & 7, b = g >> 3;
    int colq = br * 96 + hd * 48;

    // LePE weights/bias into smem
    {
        const float* lw = br ? lw1 : lw0;
        const float* lb = br ? lb1 : lb0;
        for (int idx = tid; idx < 432; idx += 416) {
            int nb = idx / 48, c = idx - nb * 48;
            sw[idx] = lw[(hd * 48 + c) * 9 + nb];
        }
        if (tid < 48) sb[tid] = lb[hd * 48 + tid];
    }
    // K/V tiles
    for (int idx = tid; idx < 392 * 12; idx += 416) {
        int j = idx / 12, c4 = idx - j * 12;
        int node = (br == 0) ? ((j / 7) * NRES + wi * 7 + (j % 7)) : (wi * 392 + j);
        const float* base = g_qkv + (size_t)(b * NTOK + node) * 1152 + colq;
        ((float4*)(sK + j * 48))[c4] = ((const float4*)(base + TDF))[c4];
        ((float4*)(sV + j * 48))[c4] = ((const float4*)(base + 2 * TDF))[c4];
    }
    __syncthreads();
    if (tid >= 392) return;

    int t = tid;
    int node = (br == 0) ? ((t / 7) * NRES + wi * 7 + (t % 7)) : (wi * 392 + t);

    const float scale = 0.14433756729740643f;   // 1/sqrt(48)
    ull s2 = pack2(scale, scale);
    ull q2[24];
    {
        const ulonglong2* qp = (const ulonglong2*)(g_qkv + (size_t)(b * NTOK + node) * 1152 + colq);
        #pragma unroll
        for (int i = 0; i < 12; i++) {
            ulonglong2 v = qp[i];
            q2[2*i]   = fmul2(v.x, s2);
            q2[2*i+1] = fmul2(v.y, s2);
        }
    }
    ull O2[24];
    #pragma unroll
    for (int i = 0; i < 24; i++) O2[i] = 0ull;
    float mval = -1e30f, l = 0.f;

    for (int j0 = 0; j0 < 392; j0 += 8) {
        float s[8];
        #pragma unroll
        for (int jj = 0; jj < 8; jj++) {
            const ulonglong2* kr = (const ulonglong2*)(sK + (j0 + jj) * 48);
            ull acc = 0ull;
            #pragma unroll
            for (int i = 0; i < 12; i++) {
                ulonglong2 kv = kr[i];
                acc = ffma2(q2[2*i],   kv.x, acc);
                acc = ffma2(q2[2*i+1], kv.y, acc);
            }
            float2 u = unpack2(acc);
            s[jj] = u.x + u.y;
        }
        float cm = s[0];
        #pragma unroll
        for (int jj = 1; jj < 8; jj++) cm = fmaxf(cm, s[jj]);
        if (cm > mval) {
            float corr = __expf(mval - cm);
            ull c2 = pack2(corr, corr);
            l *= corr;
            #pragma unroll
            for (int i = 0; i < 24; i++) O2[i] = fmul2(O2[i], c2);
            mval = cm;
        }
        #pragma unroll
        for (int jj = 0; jj < 8; jj++) {
            float p = __expf(s[jj] - mval);
            l += p;
            ull p2v = pack2(p, p);
            const ulonglong2* vr = (const ulonglong2*)(sV + (j0 + jj) * 48);
            #pragma unroll
            for (int i = 0; i < 12; i++) {
                ulonglong2 vv = vr[i];
                O2[2*i]   = ffma2(p2v, vv.x, O2[2*i]);
                O2[2*i+1] = ffma2(p2v, vv.y, O2[2*i+1]);
            }
        }
    }
    {   // normalize
        float inv = 1.f / l;
        ull iv2 = pack2(inv, inv);
        #pragma unroll
        for (int i = 0; i < 24; i++) O2[i] = fmul2(O2[i], iv2);
    }
    {   // fused LePE: depthwise 3x3 SAME within window, from smem V
        int Hd = br ? 7 : 56;
        int Wd = br ? 56 : 7;
        int h = t / Wd, w = t - (t / Wd) * Wd;
        #pragma unroll
        for (int dy = -1; dy <= 1; dy++) {
            int hh = h + dy;
            if (hh < 0 || hh >= Hd) continue;
            #pragma unroll
            for (int dx = -1; dx <= 1; dx++) {
                int ww = w + dx;
                if (ww < 0 || ww >= Wd) continue;
                int tp = hh * Wd + ww;
                int nb = (dy + 1) * 3 + (dx + 1);
                const ulonglong2* vr = (const ulonglong2*)(sV + tp * 48);
                const ulonglong2* wr = (const ulonglong2*)(sw + nb * 48);
                #pragma unroll
                for (int i = 0; i < 12; i++) {
                    ulonglong2 vv = vr[i];
                    ulonglong2 wv = wr[i];
                    O2[2*i]   = ffma2(wv.x, vv.x, O2[2*i]);
                    O2[2*i+1] = ffma2(wv.y, vv.y, O2[2*i+1]);
                }
            }
        }
    }
    float* op = out + ((size_t)(b * DIMF + colq)) * NTOK + node;
    #pragma unroll
    for (int i = 0; i < 24; i++) {
        float2 u = unpack2(O2[i]);
        op[(size_t)(2*i)     * NTOK] = u.x + sb[2*i];
        op[(size_t)(2*i + 1) * NTOK] = u.y + sb[2*i + 1];
    }
}

// ---------------------------------------------------------------------------
// Lower-line flash attention: N=3136, 3 heads, d=64, scale 0.125.
// 64 threads/block (1 query each), Bc=98 K/V rows per smem tile (3136=32*98),
// grid 49x3x4 = 588 blocks -> one wave at 4 blocks/SM (592 slots).
// ---------------------------------------------------------------------------
#define FBC 98
__global__ __launch_bounds__(64) void flash_dn_kernel(float* __restrict__ out)
{
    extern __shared__ float smem[];
    float* sK = smem;                 // [98][64]
    float* sV = smem + FBC * 64;      // [98][64]
    int tid = threadIdx.x;
    int qb = blockIdx.x;   // 0..48
    int hd = blockIdx.y;   // 0..2
    int b  = blockIdx.z;   // 0..3
    int qrow = qb * 64 + tid;
    int colq = 576 + hd * 64;

    const float scale = 0.125f;
    ull s2 = pack2(scale, scale);
    ull q2[32];
    {
        const ulonglong2* qp = (const ulonglong2*)(g_qkv + (size_t)(b * NTOK + qrow) * 1152 + colq);
        #pragma unroll
        for (int i = 0; i < 16; i++) {
            ulonglong2 v = qp[i];
            q2[2*i]   = fmul2(v.x, s2);
            q2[2*i+1] = fmul2(v.y, s2);
        }
    }
    ull O2[32];
    #pragma unroll
    for (int i = 0; i < 32; i++) O2[i] = 0ull;
    float mval = -1e30f, l = 0.f;

    for (int kt = 0; kt < NTOK / FBC; kt++) {
        __syncthreads();
        for (int idx = tid; idx < FBC * 16; idx += 64) {
            int r = idx >> 4, c4 = idx & 15;
            const float* base = g_qkv + (size_t)(b * NTOK + kt * FBC + r) * 1152 + colq;
            ((float4*)(sK + r * 64))[c4] = ((const float4*)(base + TDF))[c4];
            ((float4*)(sV + r * 64))[c4] = ((const float4*)(base + 2 * TDF))[c4];
        }
        __syncthreads();

        for (int j0 = 0; j0 < FBC; j0 += 7) {
            float s[7];
            #pragma unroll
            for (int jj = 0; jj < 7; jj++) {
                const ulonglong2* kr = (const ulonglong2*)(sK + (j0 + jj) * 64);
                ull acc = 0ull;
                #pragma unroll
                for (int i = 0; i < 16; i++) {
                    ulonglong2 kv = kr[i];
                    acc = ffma2(q2[2*i],   kv.x, acc);
                    acc = ffma2(q2[2*i+1], kv.y, acc);
                }
                float2 u = unpack2(acc);
                s[jj] = u.x + u.y;
            }
            float cm = s[0];
            #pragma unroll
            for (int jj = 1; jj < 7; jj++) cm = fmaxf(cm, s[jj]);
            if (cm > mval) {
                float corr = __expf(mval - cm);
                ull c2 = pack2(corr, corr);
                l *= corr;
                #pragma unroll
                for (int i = 0; i < 32; i++) O2[i] = fmul2(O2[i], c2);
                mval = cm;
            }
            #pragma unroll
            for (int jj = 0; jj < 7; jj++) {
                float p = __expf(s[jj] - mval);
                l += p;
                ull p2v = pack2(p, p);
                const ulonglong2* vr = (const ulonglong2*)(sV + (j0 + jj) * 64);
                #pragma unroll
                for (int i = 0; i < 16; i++) {
                    ulonglong2 vv = vr[i];
                    O2[2*i]   = ffma2(p2v, vv.x, O2[2*i]);
                    O2[2*i+1] = ffma2(p2v, vv.y, O2[2*i+1]);
                }
            }
        }
    }
    float inv = 1.f / l;
    ull iv2 = pack2(inv, inv);
    float* op = out + ((size_t)(b * DIMF + TDF + hd * 64)) * NTOK + qrow;
    #pragma unroll
    for (int i = 0; i < 32; i++) {
        float2 u = unpack2(fmul2(O2[i], iv2));
        op[(size_t)(2*i)     * NTOK] = u.x;
        op[(size_t)(2*i + 1) * NTOK] = u.y;
    }
}

// ---------------------------------------------------------------------------
extern "C" void kernel_launch(void* const* d_in, const int* in_sizes, int n_in,
                              void* d_out, int out_size)
{
    const float* xa  = (const float*)d_in[0];
    const float* p1  = (const float*)d_in[1];
    const float* p2  = (const float*)d_in[2];
    const float* wu  = (const float*)d_in[3];
    const float* wd  = (const float*)d_in[4];
    const float* lw0 = (const float*)d_in[5];
    const float* lb0 = (const float*)d_in[6];
    const float* lw1 = (const float*)d_in[7];
    const float* lb1 = (const float*)d_in[8];
    float* out = (float*)d_out;

    const int cswin_smem = (2 * 392 * 48 + 9 * 48 + 48) * 4;   // 152448 B
    const int flash_smem = FBC * 128 * 4;                      // 50176 B
    cudaFuncSetAttribute(cswin_kernel,
                         cudaFuncAttributeMaxDynamicSharedMemorySize, cswin_smem);
    cudaFuncSetAttribute(flash_dn_kernel,
                         cudaFuncAttributeMaxDynamicSharedMemorySize, flash_smem);

    gemm1_kernel<<<dim3(MTOT / 256, DIMF / 64), 256>>>(xa, p1, p2);
    gemm2_kernel<<<dim3(MTOT / 256, 1152 / 64), 256>>>(wu, wd);
    cswin_kernel<<<dim3(32, 2, 2), 416, cswin_smem>>>(lw0, lb0, lw1, lb1, out);
    flash_dn_kernel<<<dim3(NTOK / 64, 3, NB), 64, flash_smem>>>(out);
}